// round 2
// baseline (speedup 1.0000x reference)
#include <cuda_runtime.h>

#define NB   4
#define CIN  512
#define COUT 64
#define SS   16384   // T*H*W = 16*32*32
#define NSPLIT 32    // split-K factor for final contraction

// ---------------- scratch (device globals; no allocs allowed) ----------------
__device__ float g_y1  [NB * CIN * SS];   // 128 MB
__device__ float g_feat[NB * CIN * SS];   // 128 MB
__device__ float g_h1  [NB * 128 * SS];   //  32 MB
__device__ float g_h2  [NB *  64 * SS];   //  16 MB
__device__ float g_occ [NB *  64 * SS];   //  16 MB

// ---------------- generic tiled GEMM: Y[b] = act(W * X[b] + bias) ------------
// W: (M,K) row-major.  X: (B,K,S) with S contiguous.  Y: (B,M,S).
// ACT: 0 = none, 1 = relu, 2 = abs
template<int BM, int BN, int BK, int TM, int TN, int ACT>
__global__ __launch_bounds__(256)
void gemm_bias_act(const float* __restrict__ X, const float* __restrict__ W,
                   const float* __restrict__ bias, float* __restrict__ Y,
                   int M, int K)
{
    const int S = SS;
    const int b = blockIdx.z;
    const float* Xb = X + (long)b * K * S;
    float*       Yb = Y + (long)b * M * S;
    const int n0 = blockIdx.x * BN;
    const int m0 = blockIdx.y * BM;

    __shared__ float Wsm[BK][BM + 4];
    __shared__ float Xsm[BK][BN + 4];

    const int t  = threadIdx.x;
    const int tn = t % (BN / TN);
    const int tm = t / (BN / TN);

    float acc[TM][TN];
#pragma unroll
    for (int i = 0; i < TM; i++)
#pragma unroll
        for (int j = 0; j < TN; j++) acc[i][j] = 0.f;

    // load mappings (each thread loads one float4 per tile; sizes divide exactly)
    const int wm = (t * 4) / BK;          // W tile: BM x BK
    const int wk = (t * 4) % BK;
    const int xk = (t * 4) / BN;          // X tile: BK x BN
    const int xn = (t * 4) % BN;

    for (int k0 = 0; k0 < K; k0 += BK) {
        float4 w4 = *(const float4*)(W + (long)(m0 + wm) * K + k0 + wk);
        Wsm[wk + 0][wm] = w4.x;
        Wsm[wk + 1][wm] = w4.y;
        Wsm[wk + 2][wm] = w4.z;
        Wsm[wk + 3][wm] = w4.w;
        float4 x4 = *(const float4*)(Xb + (long)(k0 + xk) * S + n0 + xn);
        *(float4*)&Xsm[xk][xn] = x4;
        __syncthreads();

#pragma unroll
        for (int kk = 0; kk < BK; kk++) {
            float a[TM], bb[TN];
#pragma unroll
            for (int i = 0; i < TM; i += 4) {
                float4 v = *(const float4*)&Wsm[kk][tm * TM + i];
                a[i] = v.x; a[i + 1] = v.y; a[i + 2] = v.z; a[i + 3] = v.w;
            }
#pragma unroll
            for (int j = 0; j < TN; j += 4) {
                float4 v = *(const float4*)&Xsm[kk][tn * TN + j];
                bb[j] = v.x; bb[j + 1] = v.y; bb[j + 2] = v.z; bb[j + 3] = v.w;
            }
#pragma unroll
            for (int i = 0; i < TM; i++)
#pragma unroll
                for (int j = 0; j < TN; j++) acc[i][j] += a[i] * bb[j];
        }
        __syncthreads();
    }

    // epilogue: bias + activation, vectorized stores
#pragma unroll
    for (int i = 0; i < TM; i++) {
        const int m = m0 + tm * TM + i;
        const float bv = (bias != nullptr) ? bias[m] : 0.f;
        float* yrow = Yb + (long)m * S + n0 + tn * TN;
#pragma unroll
        for (int j = 0; j < TN; j += 4) {
            float4 v;
            float e0 = acc[i][j + 0] + bv;
            float e1 = acc[i][j + 1] + bv;
            float e2 = acc[i][j + 2] + bv;
            float e3 = acc[i][j + 3] + bv;
            if (ACT == 1) { e0 = fmaxf(e0, 0.f); e1 = fmaxf(e1, 0.f);
                            e2 = fmaxf(e2, 0.f); e3 = fmaxf(e3, 0.f); }
            if (ACT == 2) { e0 = fabsf(e0); e1 = fabsf(e1);
                            e2 = fabsf(e2); e3 = fabsf(e3); }
            v.x = e0; v.y = e1; v.z = e2; v.w = e3;
            *(float4*)(yrow + j) = v;
        }
    }
}

// ------ final contraction: out[b,o,c] = (1/S) * sum_s occ[b,o,s]*feat[b,c,s] -
// A = occ (B,64,S), F = feat (B,512,S). Split-K over s with atomicAdd.
__global__ __launch_bounds__(256)
void pool_contract(const float* __restrict__ Occ, const float* __restrict__ Feat,
                   float* __restrict__ out)
{
    const int S = SS;
    const int bz = blockIdx.z;
    const int b  = bz / NSPLIT;
    const int sp = bz % NSPLIT;
    const int chunk = S / NSPLIT;           // 512
    const int sbeg  = sp * chunk;

    const float* Ab = Occ  + (long)b * COUT * S;
    const float* Fb = Feat + (long)b * CIN  * S;
    const int n0 = blockIdx.x * 64;         // c tile

    __shared__ float As[16][64 + 4];
    __shared__ float Bs[16][64 + 4];

    const int t  = threadIdx.x;
    const int tn = t % 16;
    const int tm = t / 16;
    const int lrow = t >> 2;                // 0..63
    const int lk   = (t & 3) * 4;           // 0,4,8,12

    float acc[4][4];
#pragma unroll
    for (int i = 0; i < 4; i++)
#pragma unroll
        for (int j = 0; j < 4; j++) acc[i][j] = 0.f;

    for (int s0 = sbeg; s0 < sbeg + chunk; s0 += 16) {
        float4 a4 = *(const float4*)(Ab + (long)lrow * S + s0 + lk);
        As[lk + 0][lrow] = a4.x; As[lk + 1][lrow] = a4.y;
        As[lk + 2][lrow] = a4.z; As[lk + 3][lrow] = a4.w;
        float4 f4 = *(const float4*)(Fb + (long)(n0 + lrow) * S + s0 + lk);
        Bs[lk + 0][lrow] = f4.x; Bs[lk + 1][lrow] = f4.y;
        Bs[lk + 2][lrow] = f4.z; Bs[lk + 3][lrow] = f4.w;
        __syncthreads();

#pragma unroll
        for (int kk = 0; kk < 16; kk++) {
            float4 av = *(const float4*)&As[kk][tm * 4];
            float4 bv = *(const float4*)&Bs[kk][tn * 4];
            float a[4] = {av.x, av.y, av.z, av.w};
            float c[4] = {bv.x, bv.y, bv.z, bv.w};
#pragma unroll
            for (int i = 0; i < 4; i++)
#pragma unroll
                for (int j = 0; j < 4; j++) acc[i][j] += a[i] * c[j];
        }
        __syncthreads();
    }

    const float scale = 1.0f / (float)S;
#pragma unroll
    for (int i = 0; i < 4; i++)
#pragma unroll
        for (int j = 0; j < 4; j++) {
            const int o = tm * 4 + i;
            const int c = n0 + tn * 4 + j;
            atomicAdd(&out[((long)b * COUT + o) * CIN + c], acc[i][j] * scale);
        }
}

__global__ void zero_out_kernel(float* o, int n)
{
    int i = blockIdx.x * blockDim.x + threadIdx.x;
    if (i < n) o[i] = 0.f;
}

// ---------------------------------------------------------------------------
extern "C" void kernel_launch(void* const* d_in, const int* in_sizes, int n_in,
                              void* d_out, int out_size)
{
    const float* x      = (const float*)d_in[0];
    const float* w_add1 = (const float*)d_in[1];
    const float* b_add1 = (const float*)d_in[2];
    const float* w_add2 = (const float*)d_in[3];
    const float* b_add2 = (const float*)d_in[4];
    const float* w_occ1 = (const float*)d_in[5];
    const float* b_occ1 = (const float*)d_in[6];
    const float* w_occ2 = (const float*)d_in[7];
    const float* b_occ2 = (const float*)d_in[8];
    const float* w_occ3 = (const float*)d_in[9];
    float* out = (float*)d_out;

    float *y1, *feat, *h1, *h2, *occ;
    cudaGetSymbolAddress((void**)&y1,   g_y1);
    cudaGetSymbolAddress((void**)&feat, g_feat);
    cudaGetSymbolAddress((void**)&h1,   g_h1);
    cudaGetSymbolAddress((void**)&h2,   g_h2);
    cudaGetSymbolAddress((void**)&occ,  g_occ);

    zero_out_kernel<<<(out_size + 255) / 256, 256>>>(out, out_size);

    // occ path: 512 -> 128 (relu) -> 64 (relu) -> 64 (abs, no bias)
    gemm_bias_act<128,128,8,8,8,1><<<dim3(SS/128, 1, NB), 256>>>(x,  w_occ1, b_occ1, h1, 128, 512);
    gemm_bias_act< 64, 64,16,4,4,1><<<dim3(SS/64,  1, NB), 256>>>(h1, w_occ2, b_occ2, h2,  64, 128);
    gemm_bias_act< 64, 64,16,4,4,2><<<dim3(SS/64,  1, NB), 256>>>(h2, w_occ3, nullptr, occ, 64,  64);

    // add path: 512 -> 512 (relu) -> 512
    gemm_bias_act<128,128,8,8,8,1><<<dim3(SS/128, 4, NB), 256>>>(x,  w_add1, b_add1, y1,  512, 512);
    gemm_bias_act<128,128,8,8,8,0><<<dim3(SS/128, 4, NB), 256>>>(y1, w_add2, b_add2, feat,512, 512);

    // out[b,o,c] = mean_s occ * feat
    pool_contract<<<dim3(CIN/64, 1, NB * NSPLIT), 256>>>(occ, feat, out);
}

// round 4
// speedup vs baseline: 1.9011x; 1.9011x over previous
#include <cuda_runtime.h>
#include <cuda_bf16.h>
#include <mma.h>
#include <cstdint>

using namespace nvcuda;

#define NB   4
#define CIN  512
#define COUT 64
#define SS   16384   // T*H*W
#define NSPLIT 32

// ---------------- scratch (device globals; no allocs allowed) ----------------
__device__ __nv_bfloat16 g_xt_hi[(size_t)NB * SS * CIN];
__device__ __nv_bfloat16 g_xt_lo[(size_t)NB * SS * CIN];
__device__ __nv_bfloat16 g_yt_hi[(size_t)NB * SS * CIN];
__device__ __nv_bfloat16 g_yt_lo[(size_t)NB * SS * CIN];
__device__ float g_feat[(size_t)NB * CIN * SS];
__device__ float g_h1  [(size_t)NB * 128 * SS];
__device__ float g_h2  [(size_t)NB *  64 * SS];
__device__ float g_occ [(size_t)NB *  64 * SS];
__device__ __nv_bfloat16 g_w1hi[CIN*CIN], g_w1lo[CIN*CIN];
__device__ __nv_bfloat16 g_w2hi[CIN*CIN], g_w2lo[CIN*CIN];
__device__ __nv_bfloat16 g_wo1hi[128*CIN], g_wo1lo[128*CIN];

// ---------------- helpers ----------------------------------------------------
__device__ __forceinline__ uint32_t smem_u32(const void* p) {
    uint32_t a;
    asm("{ .reg .u64 t; cvta.to.shared.u64 t, %1; cvt.u32.u64 %0, t; }" : "=r"(a) : "l"(p));
    return a;
}
__device__ __forceinline__ void cp16(uint32_t dst, const void* src) {
    asm volatile("cp.async.cg.shared.global [%0], [%1], 16;" :: "r"(dst), "l"(src));
}
__device__ __forceinline__ void cp_commit() {
    asm volatile("cp.async.commit_group;" ::: "memory");
}
template<int N>
__device__ __forceinline__ void cp_wait() {
    asm volatile("cp.async.wait_group %0;" :: "n"(N) : "memory");
}

// ---------------- HMMA GEMM: D(128x128) = W(128,512) x Act^T(128,512)^T ------
// A = W rows (M,512) bf16 hi/lo K-major. B = act^T rows (B*S,512) bf16 hi/lo.
// 3-term product: Ahi*Bhi + Ahi*Blo + Alo*Bhi  (fp32 accum)
// MODE 0: OutF32 (B, M, S) with bias+ACT.
// MODE 1: bf16 hi/lo transposed out (B, S, 512) at col offset m0 (bias+ACT).
#define STAGE_B  40960          // 4 tiles x 128 rows x 80B
#define TILE_B   10240
#define HSMEM    81920
template<int MODE, int ACT>
__global__ __launch_bounds__(256)
void hmma_gemm(const __nv_bfloat16* __restrict__ Whi, const __nv_bfloat16* __restrict__ Wlo,
               const __nv_bfloat16* __restrict__ Bh,  const __nv_bfloat16* __restrict__ Bl,
               const float* __restrict__ bias,
               float* __restrict__ OutF,
               __nv_bfloat16* __restrict__ OutTh, __nv_bfloat16* __restrict__ OutTl,
               int M)
{
    extern __shared__ __align__(128) char smem[];
    const int t = threadIdx.x, wid = t >> 5;
    const int n0 = blockIdx.x * 128, m0 = blockIdx.y * 128, b = blockIdx.z;
    const long brow = (long)b * SS + n0;
    const uint32_t sb = smem_u32(smem);

    const int wm = wid & 3;        // 4 warp rows  -> 32 m each
    const int wn = wid >> 2;       // 2 warp cols  -> 64 n each

    const __nv_bfloat16* bases[4] = {
        Whi + (long)m0 * 512, Wlo + (long)m0 * 512,
        Bh + brow * 512, Bl + brow * 512 };

    // tiles in smem: row-major [128][40] bf16 (80B rows, +16B pad per row)
    auto load_chunk = [&](int c, int st) {
        const int k0 = c * 32;
#pragma unroll
        for (int i = 0; i < 8; ++i) {
            const int vid = t + i * 256;
            const int tile = vid >> 9;
            const int r    = (vid >> 2) & 127;
            const int v    = vid & 3;
            cp16(sb + st * STAGE_B + tile * TILE_B + r * 80 + v * 16,
                 bases[tile] + (long)r * 512 + k0 + v * 8);
        }
        cp_commit();
    };

    wmma::fragment<wmma::accumulator, 16, 16, 16, float> acc[2][4];
#pragma unroll
    for (int i = 0; i < 2; ++i)
#pragma unroll
        for (int j = 0; j < 4; ++j) wmma::fill_fragment(acc[i][j], 0.0f);

    load_chunk(0, 0);

    for (int c = 0; c < 16; ++c) {
        const int st = c & 1;
        if (c + 1 < 16) { load_chunk(c + 1, st ^ 1); cp_wait<1>(); }
        else            { cp_wait<0>(); }
        __syncthreads();

        const __nv_bfloat16* Ah  = (const __nv_bfloat16*)(smem + st * STAGE_B);
        const __nv_bfloat16* Al  = Ah + 5120;
        const __nv_bfloat16* Bhs = Ah + 10240;
        const __nv_bfloat16* Bls = Ah + 15360;

#pragma unroll
        for (int kk = 0; kk < 32; kk += 16) {
            wmma::fragment<wmma::matrix_a, 16, 16, 16, __nv_bfloat16, wmma::row_major> fah[2], fal[2];
            wmma::fragment<wmma::matrix_b, 16, 16, 16, __nv_bfloat16, wmma::col_major> fbh[4], fbl[4];
#pragma unroll
            for (int i = 0; i < 2; ++i) {
                wmma::load_matrix_sync(fah[i], Ah + (wm * 32 + i * 16) * 40 + kk, 40);
                wmma::load_matrix_sync(fal[i], Al + (wm * 32 + i * 16) * 40 + kk, 40);
            }
#pragma unroll
            for (int j = 0; j < 4; ++j) {
                wmma::load_matrix_sync(fbh[j], Bhs + (wn * 64 + j * 16) * 40 + kk, 40);
                wmma::load_matrix_sync(fbl[j], Bls + (wn * 64 + j * 16) * 40 + kk, 40);
            }
#pragma unroll
            for (int i = 0; i < 2; ++i)
#pragma unroll
                for (int j = 0; j < 4; ++j) {
                    wmma::mma_sync(acc[i][j], fah[i], fbh[j], acc[i][j]);
                    wmma::mma_sync(acc[i][j], fah[i], fbl[j], acc[i][j]);
                    wmma::mma_sync(acc[i][j], fal[i], fbh[j], acc[i][j]);
                }
        }
        __syncthreads();
    }

    // ---- epilogue via smem (reuse stage memory) ----
    float* Dsm = (float*)smem;    // MODE0: [m][n] 128x132 ; MODE1: [n][m] 128x132
    if (MODE == 0) {
#pragma unroll
        for (int i = 0; i < 2; ++i)
#pragma unroll
            for (int j = 0; j < 4; ++j)
                wmma::store_matrix_sync(Dsm + (wm * 32 + i * 16) * 132 + wn * 64 + j * 16,
                                        acc[i][j], 132, wmma::mem_row_major);
        __syncthreads();
        const int r  = t >> 1;
        const int cb = (t & 1) * 64;
        const float bv = bias ? bias[m0 + r] : 0.f;
        float* yr = OutF + ((long)b * M + m0 + r) * SS + n0 + cb;
#pragma unroll
        for (int j = 0; j < 64; j += 4) {
            float4 v;
            float e0 = Dsm[r * 132 + cb + j + 0] + bv;
            float e1 = Dsm[r * 132 + cb + j + 1] + bv;
            float e2 = Dsm[r * 132 + cb + j + 2] + bv;
            float e3 = Dsm[r * 132 + cb + j + 3] + bv;
            if (ACT == 1) { e0=fmaxf(e0,0.f); e1=fmaxf(e1,0.f);
                            e2=fmaxf(e2,0.f); e3=fmaxf(e3,0.f); }
            v.x=e0; v.y=e1; v.z=e2; v.w=e3;
            *(float4*)(yr + j) = v;
        }
    } else {
#pragma unroll
        for (int i = 0; i < 2; ++i)
#pragma unroll
            for (int j = 0; j < 4; ++j)
                wmma::store_matrix_sync(Dsm + (wn * 64 + j * 16) * 132 + wm * 32 + i * 16,
                                        acc[i][j], 132, wmma::mem_col_major);
        __syncthreads();
        const int n  = t >> 1;
        const int mb = (t & 1) * 64;
        union U8 { uint4 u; __nv_bfloat16 h[8]; };
        const long off = ((long)b * SS + n0 + n) * 512 + m0 + mb;
#pragma unroll
        for (int g = 0; g < 8; ++g) {
            U8 uh, ul;
#pragma unroll
            for (int e = 0; e < 8; ++e) {
                const int m = mb + g * 8 + e;
                float v = Dsm[n * 132 + m] + (bias ? bias[m0 + m] : 0.f);
                if (ACT == 1) v = fmaxf(v, 0.f);
                __nv_bfloat16 hh = __float2bfloat16(v);
                uh.h[e] = hh;
                ul.h[e] = __float2bfloat16(v - __bfloat162float(hh));
            }
            *(uint4*)(OutTh + off + g * 8) = uh.u;
            *(uint4*)(OutTl + off + g * 8) = ul.u;
        }
    }
}

// ---------------- pre-passes --------------------------------------------------
__global__ __launch_bounds__(256)
void transpose_split(const float* __restrict__ X,
                     __nv_bfloat16* __restrict__ H, __nv_bfloat16* __restrict__ L)
{
    __shared__ float tile[32][33];
    const int s0 = blockIdx.x * 32, c0 = blockIdx.y * 32, b = blockIdx.z;
    const int tx = threadIdx.x, ty = threadIdx.y;   // 32 x 8
    const float* Xb = X + ((long)b * CIN + c0) * SS + s0;
#pragma unroll
    for (int j = 0; j < 4; ++j)
        tile[ty + 8 * j][tx] = Xb[(long)(ty + 8 * j) * SS + tx];
    __syncthreads();
#pragma unroll
    for (int j = 0; j < 4; ++j) {
        const int s = ty + 8 * j;
        float v = tile[tx][s];
        const long off = ((long)b * SS + s0 + s) * CIN + c0 + tx;
        __nv_bfloat16 hi = __float2bfloat16(v);
        H[off] = hi;
        L[off] = __float2bfloat16(v - __bfloat162float(hi));
    }
}

__global__ void wsplit(const float* __restrict__ W,
                       __nv_bfloat16* __restrict__ H, __nv_bfloat16* __restrict__ L, int n)
{
    int i = blockIdx.x * 256 + threadIdx.x;
    if (i < n) {
        float v = W[i];
        __nv_bfloat16 h = __float2bfloat16(v);
        H[i] = h;
        L[i] = __float2bfloat16(v - __bfloat162float(h));
    }
}

// ---------------- small SIMT GEMM for occ2/occ3 -------------------------------
template<int BM, int BN, int BK, int TM, int TN, int ACT>
__global__ __launch_bounds__(256)
void gemm_bias_act(const float* __restrict__ X, const float* __restrict__ W,
                   const float* __restrict__ bias, float* __restrict__ Y,
                   int M, int K)
{
    const int S = SS;
    const int b = blockIdx.z;
    const float* Xb = X + (long)b * K * S;
    float*       Yb = Y + (long)b * M * S;
    const int n0 = blockIdx.x * BN;
    const int m0 = blockIdx.y * BM;

    __shared__ float Wsm[BK][BM + 4];
    __shared__ float Xsm[BK][BN + 4];

    const int t  = threadIdx.x;
    const int tn = t % (BN / TN);
    const int tm = t / (BN / TN);

    float acc[TM][TN];
#pragma unroll
    for (int i = 0; i < TM; i++)
#pragma unroll
        for (int j = 0; j < TN; j++) acc[i][j] = 0.f;

    const int wm = (t * 4) / BK;
    const int wk = (t * 4) % BK;
    const int xk = (t * 4) / BN;
    const int xn = (t * 4) % BN;

    for (int k0 = 0; k0 < K; k0 += BK) {
        float4 w4 = *(const float4*)(W + (long)(m0 + wm) * K + k0 + wk);
        Wsm[wk + 0][wm] = w4.x; Wsm[wk + 1][wm] = w4.y;
        Wsm[wk + 2][wm] = w4.z; Wsm[wk + 3][wm] = w4.w;
        float4 x4 = *(const float4*)(Xb + (long)(k0 + xk) * S + n0 + xn);
        *(float4*)&Xsm[xk][xn] = x4;
        __syncthreads();

#pragma unroll
        for (int kk = 0; kk < BK; kk++) {
            float a[TM], bb[TN];
#pragma unroll
            for (int i = 0; i < TM; i += 4) {
                float4 v = *(const float4*)&Wsm[kk][tm * TM + i];
                a[i] = v.x; a[i+1] = v.y; a[i+2] = v.z; a[i+3] = v.w;
            }
#pragma unroll
            for (int j = 0; j < TN; j += 4) {
                float4 v = *(const float4*)&Xsm[kk][tn * TN + j];
                bb[j] = v.x; bb[j+1] = v.y; bb[j+2] = v.z; bb[j+3] = v.w;
            }
#pragma unroll
            for (int i = 0; i < TM; i++)
#pragma unroll
                for (int j = 0; j < TN; j++) acc[i][j] += a[i] * bb[j];
        }
        __syncthreads();
    }

#pragma unroll
    for (int i = 0; i < TM; i++) {
        const int m = m0 + tm * TM + i;
        const float bv = (bias != nullptr) ? bias[m] : 0.f;
        float* yrow = Yb + (long)m * S + n0 + tn * TN;
#pragma unroll
        for (int j = 0; j < TN; j += 4) {
            float4 v;
            float e0 = acc[i][j+0] + bv, e1 = acc[i][j+1] + bv;
            float e2 = acc[i][j+2] + bv, e3 = acc[i][j+3] + bv;
            if (ACT == 1) { e0=fmaxf(e0,0.f); e1=fmaxf(e1,0.f);
                            e2=fmaxf(e2,0.f); e3=fmaxf(e3,0.f); }
            if (ACT == 2) { e0=fabsf(e0); e1=fabsf(e1); e2=fabsf(e2); e3=fabsf(e3); }
            v.x=e0; v.y=e1; v.z=e2; v.w=e3;
            *(float4*)(yrow + j) = v;
        }
    }
}

// ---------------- final contraction (split-K atomics) -------------------------
__global__ __launch_bounds__(256)
void pool_contract(const float* __restrict__ Occ, const float* __restrict__ Feat,
                   float* __restrict__ out)
{
    const int S = SS;
    const int bz = blockIdx.z;
    const int b  = bz / NSPLIT;
    const int sp = bz % NSPLIT;
    const int chunk = S / NSPLIT;
    const int sbeg  = sp * chunk;

    const float* Ab = Occ  + (long)b * COUT * S;
    const float* Fb = Feat + (long)b * CIN  * S;
    const int n0 = blockIdx.x * 64;

    __shared__ float As[16][64 + 4];
    __shared__ float Bs[16][64 + 4];

    const int t  = threadIdx.x;
    const int tn = t % 16;
    const int tm = t / 16;
    const int lrow = t >> 2;
    const int lk   = (t & 3) * 4;

    float acc[4][4];
#pragma unroll
    for (int i = 0; i < 4; i++)
#pragma unroll
        for (int j = 0; j < 4; j++) acc[i][j] = 0.f;

    for (int s0 = sbeg; s0 < sbeg + chunk; s0 += 16) {
        float4 a4 = *(const float4*)(Ab + (long)lrow * S + s0 + lk);
        As[lk+0][lrow] = a4.x; As[lk+1][lrow] = a4.y;
        As[lk+2][lrow] = a4.z; As[lk+3][lrow] = a4.w;
        float4 f4 = *(const float4*)(Fb + (long)(n0 + lrow) * S + s0 + lk);
        Bs[lk+0][lrow] = f4.x; Bs[lk+1][lrow] = f4.y;
        Bs[lk+2][lrow] = f4.z; Bs[lk+3][lrow] = f4.w;
        __syncthreads();

#pragma unroll
        for (int kk = 0; kk < 16; kk++) {
            float4 av = *(const float4*)&As[kk][tm * 4];
            float4 bv = *(const float4*)&Bs[kk][tn * 4];
            float a[4] = {av.x, av.y, av.z, av.w};
            float c[4] = {bv.x, bv.y, bv.z, bv.w};
#pragma unroll
            for (int i = 0; i < 4; i++)
#pragma unroll
                for (int j = 0; j < 4; j++) acc[i][j] += a[i] * c[j];
        }
        __syncthreads();
    }

    const float scale = 1.0f / (float)S;
#pragma unroll
    for (int i = 0; i < 4; i++)
#pragma unroll
        for (int j = 0; j < 4; j++) {
            const int o = tm * 4 + i;
            const int c = n0 + tn * 4 + j;
            atomicAdd(&out[((long)b * COUT + o) * CIN + c], acc[i][j] * scale);
        }
}

__global__ void zero_out_kernel(float* o, int n)
{
    int i = blockIdx.x * blockDim.x + threadIdx.x;
    if (i < n) o[i] = 0.f;
}

// -----------------------------------------------------------------------------
extern "C" void kernel_launch(void* const* d_in, const int* in_sizes, int n_in,
                              void* d_out, int out_size)
{
    const float* x      = (const float*)d_in[0];
    const float* w_add1 = (const float*)d_in[1];
    const float* b_add1 = (const float*)d_in[2];
    const float* w_add2 = (const float*)d_in[3];
    const float* b_add2 = (const float*)d_in[4];
    const float* w_occ1 = (const float*)d_in[5];
    const float* b_occ1 = (const float*)d_in[6];
    const float* w_occ2 = (const float*)d_in[7];
    const float* b_occ2 = (const float*)d_in[8];
    const float* w_occ3 = (const float*)d_in[9];
    float* out = (float*)d_out;

    __nv_bfloat16 *xth, *xtl, *yth, *ytl, *w1h, *w1l, *w2h, *w2l, *wo1h, *wo1l;
    float *feat, *h1, *h2, *occ;
    cudaGetSymbolAddress((void**)&xth,  g_xt_hi);
    cudaGetSymbolAddress((void**)&xtl,  g_xt_lo);
    cudaGetSymbolAddress((void**)&yth,  g_yt_hi);
    cudaGetSymbolAddress((void**)&ytl,  g_yt_lo);
    cudaGetSymbolAddress((void**)&feat, g_feat);
    cudaGetSymbolAddress((void**)&h1,   g_h1);
    cudaGetSymbolAddress((void**)&h2,   g_h2);
    cudaGetSymbolAddress((void**)&occ,  g_occ);
    cudaGetSymbolAddress((void**)&w1h,  g_w1hi);
    cudaGetSymbolAddress((void**)&w1l,  g_w1lo);
    cudaGetSymbolAddress((void**)&w2h,  g_w2hi);
    cudaGetSymbolAddress((void**)&w2l,  g_w2lo);
    cudaGetSymbolAddress((void**)&wo1h, g_wo1hi);
    cudaGetSymbolAddress((void**)&wo1l, g_wo1lo);

    cudaFuncSetAttribute(hmma_gemm<1,1>, cudaFuncAttributeMaxDynamicSharedMemorySize, HSMEM);
    cudaFuncSetAttribute(hmma_gemm<0,1>, cudaFuncAttributeMaxDynamicSharedMemorySize, HSMEM);
    cudaFuncSetAttribute(hmma_gemm<0,0>, cudaFuncAttributeMaxDynamicSharedMemorySize, HSMEM);

    zero_out_kernel<<<(out_size + 255) / 256, 256>>>(out, out_size);

    // pre-passes: split weights, transpose+split activations
    wsplit<<<(CIN*CIN + 255) / 256, 256>>>(w_add1, w1h, w1l, CIN*CIN);
    wsplit<<<(CIN*CIN + 255) / 256, 256>>>(w_add2, w2h, w2l, CIN*CIN);
    wsplit<<<(128*CIN + 255) / 256, 256>>>(w_occ1, wo1h, wo1l, 128*CIN);
    transpose_split<<<dim3(SS/32, CIN/32, NB), dim3(32, 8)>>>(x, xth, xtl);

    // add1: relu(W1 x + b1) -> transposed bf16 hi/lo operand for add2
    hmma_gemm<1,1><<<dim3(SS/128, 4, NB), 256, HSMEM>>>(w1h, w1l, xth, xtl, b_add1,
                                                        nullptr, yth, ytl, CIN);
    // occ1: relu(Wo1 x + bo1) -> h1 fp32 (B,128,S)
    hmma_gemm<0,1><<<dim3(SS/128, 1, NB), 256, HSMEM>>>(wo1h, wo1l, xth, xtl, b_occ1,
                                                        h1, nullptr, nullptr, 128);
    // add2: W2 y1 + b2 -> feat fp32 (B,512,S)
    hmma_gemm<0,0><<<dim3(SS/128, 4, NB), 256, HSMEM>>>(w2h, w2l, yth, ytl, b_add2,
                                                        feat, nullptr, nullptr, CIN);

    // occ tail (SIMT)
    gemm_bias_act<64,64,16,4,4,1><<<dim3(SS/64, 1, NB), 256>>>(h1, w_occ2, b_occ2, h2, 64, 128);
    gemm_bias_act<64,64,16,4,4,2><<<dim3(SS/64, 1, NB), 256>>>(h2, w_occ3, nullptr, occ, 64, 64);

    // out[b,o,c] = mean_s occ * feat
    pool_contract<<<dim3(CIN/64, 1, NB * NSPLIT), 256>>>(occ, feat, out);
}

// round 5
// speedup vs baseline: 2.6635x; 1.4010x over previous
#include <cuda_runtime.h>
#include <cuda_bf16.h>
#include <mma.h>
#include <cstdint>

using namespace nvcuda;

#define NB   4
#define CIN  512
#define COUT 64
#define SS   16384   // T*H*W
#define NSPLIT 32

// ---------------- scratch (device globals; no allocs allowed) ----------------
__device__ __nv_bfloat16 g_xt_hi[(size_t)NB * SS * CIN];
__device__ __nv_bfloat16 g_xt_lo[(size_t)NB * SS * CIN];
__device__ float g_y1  [(size_t)NB * CIN * SS];   // relu(add1) fp32 (B,512,S)
__device__ float g_h1  [(size_t)NB * 128 * SS];
__device__ float g_h2  [(size_t)NB *  64 * SS];
__device__ float g_occ [(size_t)NB *  64 * SS];
__device__ float g_P   [(size_t)NB * COUT * CIN]; // (1/S) occ . y1^T
__device__ float g_q   [(size_t)NB * COUT];       // (1/S) sum_s occ
__device__ __nv_bfloat16 g_w1hi[CIN*CIN],  g_w1lo[CIN*CIN];
__device__ __nv_bfloat16 g_wo1hi[128*CIN], g_wo1lo[128*CIN];

// ---------------- helpers ----------------------------------------------------
__device__ __forceinline__ uint32_t smem_u32(const void* p) {
    uint32_t a;
    asm("{ .reg .u64 t; cvta.to.shared.u64 t, %1; cvt.u32.u64 %0, t; }" : "=r"(a) : "l"(p));
    return a;
}
__device__ __forceinline__ void cp16(uint32_t dst, const void* src) {
    asm volatile("cp.async.cg.shared.global [%0], [%1], 16;" :: "r"(dst), "l"(src));
}
__device__ __forceinline__ void cp_commit() {
    asm volatile("cp.async.commit_group;" ::: "memory");
}
template<int N>
__device__ __forceinline__ void cp_wait() {
    asm volatile("cp.async.wait_group %0;" :: "n"(N) : "memory");
}

// ---------------- HMMA GEMM: D(128x128) = W(128,512) x Act^T(...)^T ----------
// A = W rows (M,512) bf16 hi/lo K-major. B = act^T rows (B*S,512) bf16 hi/lo.
// 3-term product: Ahi*Bhi + Ahi*Blo + Alo*Bhi  (fp32 accum)
// OutF32 (B, M, S) with bias + optional relu.
#define STAGE_B  40960          // 4 tiles x 128 rows x 80B
#define TILE_B   10240
#define HSMEM    81920
template<int ACT>
__global__ __launch_bounds__(256)
void hmma_gemm(const __nv_bfloat16* __restrict__ Whi, const __nv_bfloat16* __restrict__ Wlo,
               const __nv_bfloat16* __restrict__ Bh,  const __nv_bfloat16* __restrict__ Bl,
               const float* __restrict__ bias, float* __restrict__ OutF, int M)
{
    extern __shared__ __align__(128) char smem[];
    const int t = threadIdx.x, wid = t >> 5;
    const int n0 = blockIdx.x * 128, m0 = blockIdx.y * 128, b = blockIdx.z;
    const long brow = (long)b * SS + n0;
    const uint32_t sb = smem_u32(smem);

    const int wm = wid & 3;        // 4 warp rows -> 32 m each
    const int wn = wid >> 2;       // 2 warp cols -> 64 n each

    const __nv_bfloat16* bases[4] = {
        Whi + (long)m0 * 512, Wlo + (long)m0 * 512,
        Bh + brow * 512, Bl + brow * 512 };

    auto load_chunk = [&](int c, int st) {
        const int k0 = c * 32;
#pragma unroll
        for (int i = 0; i < 8; ++i) {
            const int vid = t + i * 256;
            const int tile = vid >> 9;
            const int r    = (vid >> 2) & 127;
            const int v    = vid & 3;
            cp16(sb + st * STAGE_B + tile * TILE_B + r * 80 + v * 16,
                 bases[tile] + (long)r * 512 + k0 + v * 8);
        }
        cp_commit();
    };

    wmma::fragment<wmma::accumulator, 16, 16, 16, float> acc[2][4];
#pragma unroll
    for (int i = 0; i < 2; ++i)
#pragma unroll
        for (int j = 0; j < 4; ++j) wmma::fill_fragment(acc[i][j], 0.0f);

    load_chunk(0, 0);

    for (int c = 0; c < 16; ++c) {
        const int st = c & 1;
        if (c + 1 < 16) { load_chunk(c + 1, st ^ 1); cp_wait<1>(); }
        else            { cp_wait<0>(); }
        __syncthreads();

        const __nv_bfloat16* Ah  = (const __nv_bfloat16*)(smem + st * STAGE_B);
        const __nv_bfloat16* Al  = Ah + 5120;
        const __nv_bfloat16* Bhs = Ah + 10240;
        const __nv_bfloat16* Bls = Ah + 15360;

#pragma unroll
        for (int kk = 0; kk < 32; kk += 16) {
            wmma::fragment<wmma::matrix_a, 16, 16, 16, __nv_bfloat16, wmma::row_major> fah[2], fal[2];
            wmma::fragment<wmma::matrix_b, 16, 16, 16, __nv_bfloat16, wmma::col_major> fbh[4], fbl[4];
#pragma unroll
            for (int i = 0; i < 2; ++i) {
                wmma::load_matrix_sync(fah[i], Ah + (wm * 32 + i * 16) * 40 + kk, 40);
                wmma::load_matrix_sync(fal[i], Al + (wm * 32 + i * 16) * 40 + kk, 40);
            }
#pragma unroll
            for (int j = 0; j < 4; ++j) {
                wmma::load_matrix_sync(fbh[j], Bhs + (wn * 64 + j * 16) * 40 + kk, 40);
                wmma::load_matrix_sync(fbl[j], Bls + (wn * 64 + j * 16) * 40 + kk, 40);
            }
#pragma unroll
            for (int i = 0; i < 2; ++i)
#pragma unroll
                for (int j = 0; j < 4; ++j) {
                    wmma::mma_sync(acc[i][j], fah[i], fbh[j], acc[i][j]);
                    wmma::mma_sync(acc[i][j], fah[i], fbl[j], acc[i][j]);
                    wmma::mma_sync(acc[i][j], fal[i], fbh[j], acc[i][j]);
                }
        }
        __syncthreads();
    }

    // ---- epilogue via smem ----
    float* Dsm = (float*)smem;    // [m][n] 128x132
#pragma unroll
    for (int i = 0; i < 2; ++i)
#pragma unroll
        for (int j = 0; j < 4; ++j)
            wmma::store_matrix_sync(Dsm + (wm * 32 + i * 16) * 132 + wn * 64 + j * 16,
                                    acc[i][j], 132, wmma::mem_row_major);
    __syncthreads();
    const int r  = t >> 1;
    const int cb = (t & 1) * 64;
    const float bv = bias ? bias[m0 + r] : 0.f;
    float* yr = OutF + ((long)b * M + m0 + r) * SS + n0 + cb;
#pragma unroll
    for (int j = 0; j < 64; j += 4) {
        float4 v;
        float e0 = Dsm[r * 132 + cb + j + 0] + bv;
        float e1 = Dsm[r * 132 + cb + j + 1] + bv;
        float e2 = Dsm[r * 132 + cb + j + 2] + bv;
        float e3 = Dsm[r * 132 + cb + j + 3] + bv;
        if (ACT == 1) { e0=fmaxf(e0,0.f); e1=fmaxf(e1,0.f);
                        e2=fmaxf(e2,0.f); e3=fmaxf(e3,0.f); }
        v.x=e0; v.y=e1; v.z=e2; v.w=e3;
        *(float4*)(yr + j) = v;
    }
}

// ---------------- pre-passes --------------------------------------------------
__global__ __launch_bounds__(256)
void transpose_split(const float* __restrict__ X,
                     __nv_bfloat16* __restrict__ H, __nv_bfloat16* __restrict__ L)
{
    __shared__ float tile[32][33];
    const int s0 = blockIdx.x * 32, c0 = blockIdx.y * 32, b = blockIdx.z;
    const int tx = threadIdx.x, ty = threadIdx.y;   // 32 x 8
    const float* Xb = X + ((long)b * CIN + c0) * SS + s0;
#pragma unroll
    for (int j = 0; j < 4; ++j)
        tile[ty + 8 * j][tx] = Xb[(long)(ty + 8 * j) * SS + tx];
    __syncthreads();
#pragma unroll
    for (int j = 0; j < 4; ++j) {
        const int s = ty + 8 * j;
        float v = tile[tx][s];
        const long off = ((long)b * SS + s0 + s) * CIN + c0 + tx;
        __nv_bfloat16 hi = __float2bfloat16(v);
        H[off] = hi;
        L[off] = __float2bfloat16(v - __bfloat162float(hi));
    }
}

__global__ void wsplit(const float* __restrict__ W,
                       __nv_bfloat16* __restrict__ H, __nv_bfloat16* __restrict__ L, int n)
{
    int i = blockIdx.x * 256 + threadIdx.x;
    if (i < n) {
        float v = W[i];
        __nv_bfloat16 h = __float2bfloat16(v);
        H[i] = h;
        L[i] = __float2bfloat16(v - __bfloat162float(h));
    }
}

// ---------------- small SIMT GEMM for occ2/occ3 -------------------------------
template<int BM, int BN, int BK, int TM, int TN, int ACT>
__global__ __launch_bounds__(256)
void gemm_bias_act(const float* __restrict__ X, const float* __restrict__ W,
                   const float* __restrict__ bias, float* __restrict__ Y,
                   int M, int K)
{
    const int S = SS;
    const int b = blockIdx.z;
    const float* Xb = X + (long)b * K * S;
    float*       Yb = Y + (long)b * M * S;
    const int n0 = blockIdx.x * BN;
    const int m0 = blockIdx.y * BM;

    __shared__ float Wsm[BK][BM + 4];
    __shared__ float Xsm[BK][BN + 4];

    const int t  = threadIdx.x;
    const int tn = t % (BN / TN);
    const int tm = t / (BN / TN);

    float acc[TM][TN];
#pragma unroll
    for (int i = 0; i < TM; i++)
#pragma unroll
        for (int j = 0; j < TN; j++) acc[i][j] = 0.f;

    const int wm = (t * 4) / BK;
    const int wk = (t * 4) % BK;
    const int xk = (t * 4) / BN;
    const int xn = (t * 4) % BN;

    for (int k0 = 0; k0 < K; k0 += BK) {
        float4 w4 = *(const float4*)(W + (long)(m0 + wm) * K + k0 + wk);
        Wsm[wk + 0][wm] = w4.x; Wsm[wk + 1][wm] = w4.y;
        Wsm[wk + 2][wm] = w4.z; Wsm[wk + 3][wm] = w4.w;
        float4 x4 = *(const float4*)(Xb + (long)(k0 + xk) * S + n0 + xn);
        *(float4*)&Xsm[xk][xn] = x4;
        __syncthreads();

#pragma unroll
        for (int kk = 0; kk < BK; kk++) {
            float a[TM], bb[TN];
#pragma unroll
            for (int i = 0; i < TM; i += 4) {
                float4 v = *(const float4*)&Wsm[kk][tm * TM + i];
                a[i] = v.x; a[i+1] = v.y; a[i+2] = v.z; a[i+3] = v.w;
            }
#pragma unroll
            for (int j = 0; j < TN; j += 4) {
                float4 v = *(const float4*)&Xsm[kk][tn * TN + j];
                bb[j] = v.x; bb[j+1] = v.y; bb[j+2] = v.z; bb[j+3] = v.w;
            }
#pragma unroll
            for (int i = 0; i < TM; i++)
#pragma unroll
                for (int j = 0; j < TN; j++) acc[i][j] += a[i] * bb[j];
        }
        __syncthreads();
    }

#pragma unroll
    for (int i = 0; i < TM; i++) {
        const int m = m0 + tm * TM + i;
        const float bv = (bias != nullptr) ? bias[m] : 0.f;
        float* yrow = Yb + (long)m * S + n0 + tn * TN;
#pragma unroll
        for (int j = 0; j < TN; j += 4) {
            float4 v;
            float e0 = acc[i][j+0] + bv, e1 = acc[i][j+1] + bv;
            float e2 = acc[i][j+2] + bv, e3 = acc[i][j+3] + bv;
            if (ACT == 1) { e0=fmaxf(e0,0.f); e1=fmaxf(e1,0.f);
                            e2=fmaxf(e2,0.f); e3=fmaxf(e3,0.f); }
            if (ACT == 2) { e0=fabsf(e0); e1=fabsf(e1); e2=fabsf(e2); e3=fabsf(e3); }
            v.x=e0; v.y=e1; v.z=e2; v.w=e3;
            *(float4*)(yrow + j) = v;
        }
    }
}

// ------ P[b,o,k] = (1/S) sum_s occ[b,o,s] * y1[b,k,s]  (split-K atomics) ------
__global__ __launch_bounds__(256)
void pool_contract(const float* __restrict__ Occ, const float* __restrict__ Y1,
                   float* __restrict__ P)
{
    const int S = SS;
    const int bz = blockIdx.z;
    const int b  = bz / NSPLIT;
    const int sp = bz % NSPLIT;
    const int chunk = S / NSPLIT;
    const int sbeg  = sp * chunk;

    const float* Ab = Occ + (long)b * COUT * S;
    const float* Fb = Y1  + (long)b * CIN  * S;
    const int n0 = blockIdx.x * 64;

    __shared__ float As[16][64 + 4];
    __shared__ float Bs[16][64 + 4];

    const int t  = threadIdx.x;
    const int tn = t % 16;
    const int tm = t / 16;
    const int lrow = t >> 2;
    const int lk   = (t & 3) * 4;

    float acc[4][4];
#pragma unroll
    for (int i = 0; i < 4; i++)
#pragma unroll
        for (int j = 0; j < 4; j++) acc[i][j] = 0.f;

    for (int s0 = sbeg; s0 < sbeg + chunk; s0 += 16) {
        float4 a4 = *(const float4*)(Ab + (long)lrow * S + s0 + lk);
        As[lk+0][lrow] = a4.x; As[lk+1][lrow] = a4.y;
        As[lk+2][lrow] = a4.z; As[lk+3][lrow] = a4.w;
        float4 f4 = *(const float4*)(Fb + (long)(n0 + lrow) * S + s0 + lk);
        Bs[lk+0][lrow] = f4.x; Bs[lk+1][lrow] = f4.y;
        Bs[lk+2][lrow] = f4.z; Bs[lk+3][lrow] = f4.w;
        __syncthreads();

#pragma unroll
        for (int kk = 0; kk < 16; kk++) {
            float4 av = *(const float4*)&As[kk][tm * 4];
            float4 bv = *(const float4*)&Bs[kk][tn * 4];
            float a[4] = {av.x, av.y, av.z, av.w};
            float c[4] = {bv.x, bv.y, bv.z, bv.w};
#pragma unroll
            for (int i = 0; i < 4; i++)
#pragma unroll
                for (int j = 0; j < 4; j++) acc[i][j] += a[i] * c[j];
        }
        __syncthreads();
    }

    const float scale = 1.0f / (float)S;
#pragma unroll
    for (int i = 0; i < 4; i++)
#pragma unroll
        for (int j = 0; j < 4; j++) {
            const int o = tm * 4 + i;
            const int k = n0 + tn * 4 + j;
            atomicAdd(&P[((long)b * COUT + o) * CIN + k], acc[i][j] * scale);
        }
}

// ------ q[b,o] = (1/S) sum_s occ[b,o,s] --------------------------------------
__global__ __launch_bounds__(256)
void qsum(const float* __restrict__ Occ, float* __restrict__ q)
{
    const int row = blockIdx.x;                 // b*64 + o
    const float* src = Occ + (long)row * SS;
    const int t = threadIdx.x;
    float s = 0.f;
    for (int i = t * 4; i < SS; i += 1024) {
        float4 v = *(const float4*)(src + i);
        s += v.x + v.y + v.z + v.w;
    }
#pragma unroll
    for (int o = 16; o > 0; o >>= 1) s += __shfl_xor_sync(0xffffffff, s, o);
    __shared__ float red[8];
    if ((t & 31) == 0) red[t >> 5] = s;
    __syncthreads();
    if (t == 0) {
        float tot = 0.f;
#pragma unroll
        for (int i = 0; i < 8; ++i) tot += red[i];
        q[row] = tot / (float)SS;
    }
}

// ------ out[b,o,c] = sum_k P[b,o,k]*W2[c,k] + q[b,o]*b2[c] -------------------
__global__ __launch_bounds__(256)
void fin_gemm(const float* __restrict__ P, const float* __restrict__ q,
              const float* __restrict__ W2, const float* __restrict__ b2,
              float* __restrict__ out)
{
    const int b = blockIdx.z, c0 = blockIdx.x * 64;
    __shared__ float Pt[64][68];
    __shared__ float Wt[64][68];
    const int t = threadIdx.x;
    const int tm = t >> 4, tn = t & 15;

    float acc[4][4];
#pragma unroll
    for (int i = 0; i < 4; i++)
#pragma unroll
        for (int j = 0; j < 4; j++) acc[i][j] = 0.f;

    for (int k0 = 0; k0 < CIN; k0 += 64) {
#pragma unroll
        for (int i = 0; i < 4; ++i) {
            const int r  = (t >> 4) + i * 16;
            const int kc = (t & 15) * 4;
            *(float4*)&Pt[r][kc] = *(const float4*)(P + ((long)b * COUT + r) * CIN + k0 + kc);
            *(float4*)&Wt[r][kc] = *(const float4*)(W2 + (long)(c0 + r) * CIN + k0 + kc);
        }
        __syncthreads();
#pragma unroll
        for (int kk = 0; kk < 64; ++kk) {
            float a[4], w[4];
#pragma unroll
            for (int i = 0; i < 4; ++i) a[i] = Pt[tm * 4 + i][kk];
#pragma unroll
            for (int j = 0; j < 4; ++j) w[j] = Wt[tn * 4 + j][kk];
#pragma unroll
            for (int i = 0; i < 4; ++i)
#pragma unroll
                for (int j = 0; j < 4; ++j) acc[i][j] += a[i] * w[j];
        }
        __syncthreads();
    }

#pragma unroll
    for (int i = 0; i < 4; ++i) {
        const int o = tm * 4 + i;
        const float qv = q[b * COUT + o];
#pragma unroll
        for (int j = 0; j < 4; ++j) {
            const int c = c0 + tn * 4 + j;
            out[((long)b * COUT + o) * CIN + c] = acc[i][j] + qv * b2[c];
        }
    }
}

__global__ void zero_buf(float* o, int n)
{
    int i = blockIdx.x * blockDim.x + threadIdx.x;
    if (i < n) o[i] = 0.f;
}

// -----------------------------------------------------------------------------
extern "C" void kernel_launch(void* const* d_in, const int* in_sizes, int n_in,
                              void* d_out, int out_size)
{
    const float* x      = (const float*)d_in[0];
    const float* w_add1 = (const float*)d_in[1];
    const float* b_add1 = (const float*)d_in[2];
    const float* w_add2 = (const float*)d_in[3];
    const float* b_add2 = (const float*)d_in[4];
    const float* w_occ1 = (const float*)d_in[5];
    const float* b_occ1 = (const float*)d_in[6];
    const float* w_occ2 = (const float*)d_in[7];
    const float* b_occ2 = (const float*)d_in[8];
    const float* w_occ3 = (const float*)d_in[9];
    float* out = (float*)d_out;

    __nv_bfloat16 *xth, *xtl, *w1h, *w1l, *wo1h, *wo1l;
    float *y1, *h1, *h2, *occ, *P, *q;
    cudaGetSymbolAddress((void**)&xth,  g_xt_hi);
    cudaGetSymbolAddress((void**)&xtl,  g_xt_lo);
    cudaGetSymbolAddress((void**)&y1,   g_y1);
    cudaGetSymbolAddress((void**)&h1,   g_h1);
    cudaGetSymbolAddress((void**)&h2,   g_h2);
    cudaGetSymbolAddress((void**)&occ,  g_occ);
    cudaGetSymbolAddress((void**)&P,    g_P);
    cudaGetSymbolAddress((void**)&q,    g_q);
    cudaGetSymbolAddress((void**)&w1h,  g_w1hi);
    cudaGetSymbolAddress((void**)&w1l,  g_w1lo);
    cudaGetSymbolAddress((void**)&wo1h, g_wo1hi);
    cudaGetSymbolAddress((void**)&wo1l, g_wo1lo);

    cudaFuncSetAttribute(hmma_gemm<1>, cudaFuncAttributeMaxDynamicSharedMemorySize, HSMEM);

    // pre-passes
    wsplit<<<(CIN*CIN + 255) / 256, 256>>>(w_add1, w1h, w1l, CIN*CIN);
    wsplit<<<(128*CIN + 255) / 256, 256>>>(w_occ1, wo1h, wo1l, 128*CIN);
    transpose_split<<<dim3(SS/32, CIN/32, NB), dim3(32, 8)>>>(x, xth, xtl);
    zero_buf<<<(NB*COUT*CIN + 255) / 256, 256>>>(P, NB*COUT*CIN);

    // add1: y1 = relu(W1 x + b1) fp32 (B,512,S)
    hmma_gemm<1><<<dim3(SS/128, 4, NB), 256, HSMEM>>>(w1h, w1l, xth, xtl, b_add1, y1, CIN);
    // occ1: h1 = relu(Wo1 x + bo1) fp32 (B,128,S)
    hmma_gemm<1><<<dim3(SS/128, 1, NB), 256, HSMEM>>>(wo1h, wo1l, xth, xtl, b_occ1, h1, 128);

    // occ tail (SIMT)
    gemm_bias_act<64,64,16,4,4,1><<<dim3(SS/64, 1, NB), 256>>>(h1, w_occ2, b_occ2, h2, 64, 128);
    gemm_bias_act<64,64,16,4,4,2><<<dim3(SS/64, 1, NB), 256>>>(h2, w_occ3, nullptr, occ, 64, 64);

    // P = (1/S) occ . y1^T ;  q = (1/S) row-sums of occ
    pool_contract<<<dim3(CIN/64, 1, NB * NSPLIT), 256>>>(occ, y1, P);
    qsum<<<NB * COUT, 256>>>(occ, q);

    // out = P . W2^T + q b2^T
    fin_gemm<<<dim3(CIN/64, 1, NB), 256>>>(P, q, w_add2, b_add2, out);
}